// round 15
// baseline (speedup 1.0000x reference)
#include <cuda_runtime.h>
#include <cuda_fp16.h>
#include <cstdint>

// Problem constants
#define BATCH 2
#define TT    2048
#define DM    1024
#define NH    16
#define DH    64
#define BT    (BATCH * TT)   // 4096

// log2(e)/8 folded into Q projection (softmax in log2 domain)
#define QSCALE 0.1803368801111204f

// ---------------------------------------------------------------------------
// Scratch (device globals: allocation-free rule)
// ---------------------------------------------------------------------------
__device__ __half g_Qhi[BT * DM];     // [B,H,T,Dh], x log2e/8
__device__ __half g_Khi[BT * DM];     // [B,H,T,Dh]
__device__ __half g_Vhi[BT * DM];     // [B,H,T,Dh]
__device__ __half g_xhi[BT * DM];
__device__ __half g_ahi[BT * DM];     // attn out [B,T,D]
__device__ __half g_whi[4][DM * DM];

// ---------------------------------------------------------------------------
// Helpers
// ---------------------------------------------------------------------------
__device__ __forceinline__ uint32_t s2u(const void* p) {
    uint32_t a;
    asm("{ .reg .u64 t; cvta.to.shared.u64 t, %1; cvt.u32.u64 %0, t; }"
        : "=r"(a) : "l"(p));
    return a;
}

__device__ __forceinline__ void cp16(uint32_t s, const void* g) {
    asm volatile("cp.async.cg.shared.global [%0], [%1], 16;" :: "r"(s), "l"(g));
}
#define CP_COMMIT() asm volatile("cp.async.commit_group;" ::: "memory")
#define CP_WAIT(n)  asm volatile("cp.async.wait_group %0;" :: "n"(n) : "memory")

__device__ __forceinline__ void ldm_x4(uint32_t* r, uint32_t a) {
    asm volatile("ldmatrix.sync.aligned.m8n8.x4.shared.b16 {%0,%1,%2,%3}, [%4];"
                 : "=r"(r[0]), "=r"(r[1]), "=r"(r[2]), "=r"(r[3]) : "r"(a));
}

__device__ __forceinline__ void ldm_x4_trans(uint32_t* r, uint32_t a) {
    asm volatile("ldmatrix.sync.aligned.m8n8.x4.trans.shared.b16 {%0,%1,%2,%3}, [%4];"
                 : "=r"(r[0]), "=r"(r[1]), "=r"(r[2]), "=r"(r[3]) : "r"(a));
}

__device__ __forceinline__ void mma_f16(float* d, const uint32_t* a, const uint32_t* b) {
    asm volatile(
        "mma.sync.aligned.m16n8k16.row.col.f32.f16.f16.f32 "
        "{%0,%1,%2,%3}, {%4,%5,%6,%7}, {%8,%9}, {%0,%1,%2,%3};"
        : "+f"(d[0]), "+f"(d[1]), "+f"(d[2]), "+f"(d[3])
        : "r"(a[0]), "r"(a[1]), "r"(a[2]), "r"(a[3]), "r"(b[0]), "r"(b[1]));
}

__device__ __forceinline__ uint32_t ex2h2(uint32_t x) {
    uint32_t y;
    asm("ex2.approx.f16x2 %0, %1;" : "=r"(y) : "r"(x));
    return y;
}

__device__ __forceinline__ uint32_t sw128(uint32_t off) {
    return off ^ ((off >> 3) & 0x70);
}

// ---------------------------------------------------------------------------
// Fused conversion: y 0..3 -> x chunks, y 4..7 -> W_{q,k,v,o}
// ---------------------------------------------------------------------------
__global__ __launch_bounds__(256)
void cvt_all(const float* __restrict__ x,
             const float* __restrict__ W0, const float* __restrict__ W1,
             const float* __restrict__ W2, const float* __restrict__ W3)
{
    const int y = blockIdx.y;
    const float* src;
    __half* dst;
    if (y < 4) { src = x + y * (DM * DM); dst = g_xhi + y * (DM * DM); }
    else {
        src = (y == 4) ? W0 : (y == 5) ? W1 : (y == 6) ? W2 : W3;
        dst = g_whi[y - 4];
    }
    int e = (blockIdx.x * 256 + threadIdx.x) * 4;
    float4 v = *(const float4*)(src + e);
    __half2 h0 = __floats2half2_rn(v.x, v.y);
    __half2 h1 = __floats2half2_rn(v.z, v.w);
    *(uint2*)(dst + e) = make_uint2(*(uint32_t*)&h0, *(uint32_t*)&h1);
}

// ---------------------------------------------------------------------------
// mma.sync NT GEMM: C = A @ W^T. 128x128 CTA tile, 128 threads, 4 warps in
// 2x2 at 64x64 each. TWO-stage cp.async pipeline, THREE CTAs per SM
// (3 warps/SMSP so barrier stalls of one CTA are hidden by the others).
// osel: 0 -> Cext fp32; 1 -> Qhi (x QSCALE); 2 -> Khi; 3 -> Vhi.
// ---------------------------------------------------------------------------
#define SZT 16384
#define GSTG (2 * SZT)
#define SMEM_GEMM (2 * GSTG)    // 64 KB (2 stages) -> 3 CTAs/SM

__global__ __launch_bounds__(128, 3)
void gemm_mma(float* __restrict__ Cext, int asel, int wsel0, int osel0)
{
    extern __shared__ char smem[];
    const uint32_t sb = s2u(smem);

    const int wsel = wsel0 + blockIdx.z;
    const int osel = osel0 ? (osel0 + (int)blockIdx.z) : 0;

    const __half* __restrict__ Ahi = asel ? g_ahi : g_xhi;
    const __half* __restrict__ Bhi = g_whi[wsel];

    const int tid  = threadIdx.x;
    const int lane = tid & 31;
    const int wid  = tid >> 5;
    const int wm   = wid & 1;      // 2 warp-rows x 64
    const int wn   = wid >> 1;     // 2 warp-cols x 64
    const int tn   = blockIdx.x;
    const int tm   = blockIdx.y;

    float acc[4][8][4];
#pragma unroll
    for (int i = 0; i < 4; i++)
#pragma unroll
        for (int j = 0; j < 8; j++)
#pragma unroll
            for (int k = 0; k < 4; k++) acc[i][j][k] = 0.f;

    auto load_stage = [&](int s, int buf) {
        const uint32_t base = sb + buf * GSTG;
        const int k0 = s * 64;
#pragma unroll
        for (int i = 0; i < 8; i++) {
            int e = tid + i * 128;             // 0..1023
            int row = e >> 3, c = e & 7;
            uint32_t sw = sw128((uint32_t)(row * 128 + c * 16));
            cp16(base + sw,       Ahi + (size_t)(tm * 128 + row) * DM + k0 + c * 8);
            cp16(base + SZT + sw, Bhi + (size_t)(tn * 128 + row) * DM + k0 + c * 8);
        }
    };

    load_stage(0, 0); CP_COMMIT();

    for (int s = 0; s < 16; s++) {
        const int buf = s & 1;
        if (s + 1 < 16) {
            load_stage(s + 1, buf ^ 1);
            CP_COMMIT();
            CP_WAIT(1);
        } else {
            CP_WAIT(0);
        }
        __syncthreads();

        const uint32_t ab = sb + buf * GSTG;

#pragma unroll
        for (int kk = 0; kk < 4; kk++) {
            uint32_t af[4][4], bf[8][2];

            const int arow = wm * 64 + (lane & 7) + ((lane >> 3) & 1) * 8;
            const int akb  = kk * 32 + ((lane >> 4) & 1) * 16;
#pragma unroll
            for (int mf = 0; mf < 4; mf++)
                ldm_x4(af[mf], ab + sw128((uint32_t)((arow + mf * 16) * 128 + akb)));

            const int brow = wn * 64 + ((lane >> 4) & 1) * 8 + (lane & 7);
            const int bkb  = kk * 32 + ((lane >> 3) & 1) * 16;
#pragma unroll
            for (int nf2 = 0; nf2 < 4; nf2++) {
                uint32_t r[4];
                ldm_x4(r, ab + SZT + sw128((uint32_t)((brow + nf2 * 16) * 128 + bkb)));
                bf[nf2 * 2][0] = r[0]; bf[nf2 * 2][1] = r[1];
                bf[nf2 * 2 + 1][0] = r[2]; bf[nf2 * 2 + 1][1] = r[3];
            }

#pragma unroll
            for (int mf = 0; mf < 4; mf++)
#pragma unroll
                for (int nf = 0; nf < 8; nf++)
                    mma_f16(acc[mf][nf], af[mf], bf[nf]);
        }
        __syncthreads();
    }

    // ---- epilogue ----
    const float sc = (osel == 1) ? QSCALE : 1.0f;
#pragma unroll
    for (int mf = 0; mf < 4; mf++) {
#pragma unroll
        for (int nf = 0; nf < 8; nf++) {
            int r0 = tm * 128 + wm * 64 + mf * 16 + (lane >> 2);
            int c0 = tn * 128 + wn * 64 + nf * 8 + (lane & 3) * 2;
#pragma unroll
            for (int half = 0; half < 2; half++) {
                int row = r0 + half * 8;
                float vx = acc[mf][nf][half * 2];
                float vy = acc[mf][nf][half * 2 + 1];
                if (osel == 0) {
                    *(float2*)(Cext + (size_t)row * DM + c0) = make_float2(vx, vy);
                } else {
                    int b = row >> 11, t = row & 2047;
                    int h = c0 >> 6,  d = c0 & 63;
                    size_t off = ((((size_t)(b * NH + h)) * TT + t) << 6) + d;
                    __half2 hv = __floats2half2_rn(vx * sc, vy * sc);
                    __half* Dst = (osel == 1) ? g_Qhi : (osel == 2) ? g_Khi : g_Vhi;
                    *(uint32_t*)(Dst + off) = *(uint32_t*)&hv;
                }
            }
        }
    }
}

// ---------------------------------------------------------------------------
// Flash attention v7 (unchanged from round 14): max-free chunked softmax +
// 3-stage KV pipeline, one barrier per tile. 8 warps x 32 q-rows.
// ---------------------------------------------------------------------------
#define AKV 64
#define NKV (TT / AKV)
#define AS_Q   32768                    // Q staging 32K (256 rows x 128B)
#define AS_STG 16384                    // Khi 8K | Vhi 8K
#define SMEM_ATTN (AS_Q + 3 * AS_STG)   // 80 KB (3 KV stages)

__global__ __launch_bounds__(256, 1)
void attn_mma()
{
    extern __shared__ char smem[];
    const uint32_t sb = s2u(smem);
    const int tid = threadIdx.x, lane = tid & 31, wid = tid >> 5;
    const int bh = blockIdx.x, qt = blockIdx.y;
    const int b = bh >> 4, h = bh & 15;

    // ---- stage Q (256 rows x 128B) ----
    const size_t qg = ((size_t)bh * TT + qt * 256) * DH;
#pragma unroll
    for (int i = 0; i < 8; i++) {
        int e = tid + i * 256;
        int row = e >> 3, c = e & 7;
        cp16(sb + sw128((uint32_t)(row * 128 + c * 16)),
             g_Qhi + qg + (size_t)row * DH + c * 8);
    }
    CP_COMMIT();

    const size_t kvbase = (size_t)bh * TT * DH;
    auto load_kv = [&](int t, int buf) {
        const uint32_t base = sb + AS_Q + buf * AS_STG;
        const int kt = t * AKV;
#pragma unroll
        for (int i = 0; i < 2; i++) {
            int e = tid + i * 256;
            int row = e >> 3, c = e & 7;
            uint32_t sw = sw128((uint32_t)(row * 128 + c * 16));
            size_t g = kvbase + (size_t)(kt + row) * DH + c * 8;
            cp16(base + sw,        g_Khi + g);
            cp16(base + 8192 + sw, g_Vhi + g);
        }
    };
    load_kv(0, 0); CP_COMMIT();
    load_kv(1, 1); CP_COMMIT();

    // ---- cache Q fragments in registers (32 rows per warp) ----
    CP_WAIT(2);
    __syncthreads();
    uint32_t qf[4][2][4];
#pragma unroll
    for (int kk = 0; kk < 4; kk++)
#pragma unroll
        for (int mf = 0; mf < 2; mf++) {
            int arow = wid * 32 + mf * 16 + (lane & 7) + ((lane >> 3) & 1) * 8;
            int akb  = kk * 32 + ((lane >> 4) & 1) * 16;
            ldm_x4(qf[kk][mf], sb + sw128((uint32_t)(arow * 128 + akb)));
        }

    float O[2][8][4];
#pragma unroll
    for (int i = 0; i < 2; i++)
#pragma unroll
        for (int j = 0; j < 8; j++)
#pragma unroll
            for (int k = 0; k < 4; k++) O[i][j][k] = 0.f;
    float Ls[2][4] = {{0.f, 0.f, 0.f, 0.f}, {0.f, 0.f, 0.f, 0.f}};

    const uint32_t onesb[2] = {0x3C003C00u, 0x3C003C00u};

    for (int t = 0; t < NKV; t++) {
        if (t == NKV - 1) { CP_WAIT(0); } else { CP_WAIT(1); }
        __syncthreads();
        if (t + 2 < NKV) { load_kv(t + 2, (t + 2) % 3); CP_COMMIT(); }

        const uint32_t kb = sb + AS_Q + (t % 3) * AS_STG;

        // ---- 4 chunks of 16 keys: S -> ex2 -> PV, pipelined ----
#pragma unroll
        for (int c = 0; c < 4; c++) {
            float S[2][2][4];
#pragma unroll
            for (int i = 0; i < 2; i++)
#pragma unroll
                for (int j = 0; j < 2; j++)
#pragma unroll
                    for (int k = 0; k < 4; k++) S[i][j][k] = 0.f;

#pragma unroll
            for (int kk = 0; kk < 4; kk++) {
                const int brow = c * 16 + ((lane >> 4) & 1) * 8 + (lane & 7);
                const int bkb  = kk * 32 + ((lane >> 3) & 1) * 16;
                uint32_t r[4];
                ldm_x4(r, kb + sw128((uint32_t)(brow * 128 + bkb)));
                uint32_t kf0[2] = {r[0], r[1]};
                uint32_t kf1[2] = {r[2], r[3]};
#pragma unroll
                for (int mf = 0; mf < 2; mf++) {
                    mma_f16(S[mf][0], qf[kk][mf], kf0);
                    mma_f16(S[mf][1], qf[kk][mf], kf1);
                }
            }

            // P = 2^S for this chunk
            uint32_t p[2][4];
#pragma unroll
            for (int mf = 0; mf < 2; mf++) {
                __half2 a0 = __floats2half2_rn(S[mf][0][0], S[mf][0][1]);
                __half2 a1 = __floats2half2_rn(S[mf][0][2], S[mf][0][3]);
                __half2 a2 = __floats2half2_rn(S[mf][1][0], S[mf][1][1]);
                __half2 a3 = __floats2half2_rn(S[mf][1][2], S[mf][1][3]);
                p[mf][0] = ex2h2(*(uint32_t*)&a0);
                p[mf][1] = ex2h2(*(uint32_t*)&a1);
                p[mf][2] = ex2h2(*(uint32_t*)&a2);
                p[mf][3] = ex2h2(*(uint32_t*)&a3);
            }

            // PV over this 16-key chunk; l via ones-MMA
            uint32_t vf[8][2];
            const int grp = lane >> 3;
            const int vrow = c * 16 + (grp & 1) * 8 + (lane & 7);
            const int vbc  = (grp >> 1) * 16;
#pragma unroll
            for (int nf2 = 0; nf2 < 4; nf2++) {
                uint32_t r[4];
                ldm_x4_trans(r, kb + 8192 + sw128((uint32_t)(vrow * 128 + nf2 * 32 + vbc)));
                vf[nf2 * 2][0] = r[0]; vf[nf2 * 2][1] = r[1];
                vf[nf2 * 2 + 1][0] = r[2]; vf[nf2 * 2 + 1][1] = r[3];
            }
#pragma unroll
            for (int mf = 0; mf < 2; mf++) {
#pragma unroll
                for (int nf = 0; nf < 8; nf++)
                    mma_f16(O[mf][nf], p[mf], vf[nf]);
                mma_f16(Ls[mf], p[mf], onesb);
            }
        }
    }

    // ---- epilogue: normalize, write g_ahi ----
#pragma unroll
    for (int mf = 0; mf < 2; mf++) {
        float inv0 = 1.f / Ls[mf][0];
        float inv1 = 1.f / Ls[mf][2];
        int r0 = qt * 256 + wid * 32 + mf * 16 + (lane >> 2);
#pragma unroll
        for (int nf = 0; nf < 8; nf++) {
            int col = h * DH + nf * 8 + (lane & 3) * 2;
            size_t off0 = ((size_t)(b * TT) + r0) * DM + col;
            __half2 h0 = __floats2half2_rn(O[mf][nf][0] * inv0, O[mf][nf][1] * inv0);
            *(uint32_t*)(g_ahi + off0) = *(uint32_t*)&h0;
            size_t off1 = off0 + (size_t)8 * DM;
            __half2 h1 = __floats2half2_rn(O[mf][nf][2] * inv1, O[mf][nf][3] * inv1);
            *(uint32_t*)(g_ahi + off1) = *(uint32_t*)&h1;
        }
    }
}

// ---------------------------------------------------------------------------
extern "C" void kernel_launch(void* const* d_in, const int* in_sizes, int n_in,
                              void* d_out, int out_size)
{
    const float* x   = (const float*)d_in[0];
    const float* W_q = (const float*)d_in[1];
    const float* W_k = (const float*)d_in[2];
    const float* W_v = (const float*)d_in[3];
    const float* W_o = (const float*)d_in[4];
    float* out = (float*)d_out;

    cudaFuncSetAttribute(gemm_mma, cudaFuncAttributeMaxDynamicSharedMemorySize, SMEM_GEMM);
    cudaFuncSetAttribute(attn_mma, cudaFuncAttributeMaxDynamicSharedMemorySize, SMEM_ATTN);

    // fp32 -> fp16 conversions (x in 4 chunks + 4 weights, one launch)
    cvt_all<<<dim3(DM * DM / 1024, 8), 256>>>(x, W_q, W_k, W_v, W_o);

    // Q/K/V projections in one launch (1-MMA each)
    gemm_mma<<<dim3(8, 32, 3), 128, SMEM_GEMM>>>(nullptr, 0, 0, 1);

    // Max-free chunked tensor-core flash attention -> g_ahi
    attn_mma<<<dim3(BATCH * NH, TT / 256), 256, SMEM_ATTN>>>();

    // Output projection (1-MMA) -> d_out
    gemm_mma<<<dim3(8, 32, 1), 128, SMEM_GEMM>>>(out, 1, 3, 0);
}

// round 16
// speedup vs baseline: 1.0782x; 1.0782x over previous
#include <cuda_runtime.h>
#include <cuda_fp16.h>
#include <cstdint>

// Problem constants
#define BATCH 2
#define TT    2048
#define DM    1024
#define NH    16
#define DH    64
#define BT    (BATCH * TT)   // 4096

// log2(e)/8 folded into Q projection (softmax in log2 domain)
#define QSCALE 0.1803368801111204f

// ---------------------------------------------------------------------------
// Scratch (device globals: allocation-free rule)
// ---------------------------------------------------------------------------
__device__ __half g_Qhi[BT * DM];     // [B,H,T,Dh], x log2e/8
__device__ __half g_Khi[BT * DM];     // [B,H,T,Dh]
__device__ __half g_Vhi[BT * DM];     // [B,H,T,Dh]
__device__ __half g_xhi[BT * DM];
__device__ __half g_ahi[BT * DM];     // attn out [B,T,D]
__device__ __half g_whi[4][DM * DM];

// ---------------------------------------------------------------------------
// Helpers
// ---------------------------------------------------------------------------
__device__ __forceinline__ uint32_t s2u(const void* p) {
    uint32_t a;
    asm("{ .reg .u64 t; cvta.to.shared.u64 t, %1; cvt.u32.u64 %0, t; }"
        : "=r"(a) : "l"(p));
    return a;
}

__device__ __forceinline__ void cp16(uint32_t s, const void* g) {
    asm volatile("cp.async.cg.shared.global [%0], [%1], 16;" :: "r"(s), "l"(g));
}
#define CP_COMMIT() asm volatile("cp.async.commit_group;" ::: "memory")
#define CP_WAIT(n)  asm volatile("cp.async.wait_group %0;" :: "n"(n) : "memory")

__device__ __forceinline__ void ldm_x4(uint32_t* r, uint32_t a) {
    asm volatile("ldmatrix.sync.aligned.m8n8.x4.shared.b16 {%0,%1,%2,%3}, [%4];"
                 : "=r"(r[0]), "=r"(r[1]), "=r"(r[2]), "=r"(r[3]) : "r"(a));
}

__device__ __forceinline__ void ldm_x4_trans(uint32_t* r, uint32_t a) {
    asm volatile("ldmatrix.sync.aligned.m8n8.x4.trans.shared.b16 {%0,%1,%2,%3}, [%4];"
                 : "=r"(r[0]), "=r"(r[1]), "=r"(r[2]), "=r"(r[3]) : "r"(a));
}

__device__ __forceinline__ void mma_f16(float* d, const uint32_t* a, const uint32_t* b) {
    asm volatile(
        "mma.sync.aligned.m16n8k16.row.col.f32.f16.f16.f32 "
        "{%0,%1,%2,%3}, {%4,%5,%6,%7}, {%8,%9}, {%0,%1,%2,%3};"
        : "+f"(d[0]), "+f"(d[1]), "+f"(d[2]), "+f"(d[3])
        : "r"(a[0]), "r"(a[1]), "r"(a[2]), "r"(a[3]), "r"(b[0]), "r"(b[1]));
}

__device__ __forceinline__ uint32_t ex2h2(uint32_t x) {
    uint32_t y;
    asm("ex2.approx.f16x2 %0, %1;" : "=r"(y) : "r"(x));
    return y;
}

__device__ __forceinline__ uint32_t sw128(uint32_t off) {
    return off ^ ((off >> 3) & 0x70);
}

// ---------------------------------------------------------------------------
// Fused conversion: y 0..3 -> x chunks, y 4..7 -> W_{q,k,v,o}
// ---------------------------------------------------------------------------
__global__ __launch_bounds__(256)
void cvt_all(const float* __restrict__ x,
             const float* __restrict__ W0, const float* __restrict__ W1,
             const float* __restrict__ W2, const float* __restrict__ W3)
{
    const int y = blockIdx.y;
    const float* src;
    __half* dst;
    if (y < 4) { src = x + y * (DM * DM); dst = g_xhi + y * (DM * DM); }
    else {
        src = (y == 4) ? W0 : (y == 5) ? W1 : (y == 6) ? W2 : W3;
        dst = g_whi[y - 4];
    }
    int e = (blockIdx.x * 256 + threadIdx.x) * 4;
    float4 v = *(const float4*)(src + e);
    __half2 h0 = __floats2half2_rn(v.x, v.y);
    __half2 h1 = __floats2half2_rn(v.z, v.w);
    *(uint2*)(dst + e) = make_uint2(*(uint32_t*)&h0, *(uint32_t*)&h1);
}

// ---------------------------------------------------------------------------
// mma.sync NT GEMM (reverted to round-13 configuration — best measured).
// 128x128 CTA tile, 128 threads, 4 warps at 64x64, 2-stage cp.async, 2 CTA/SM.
// osel: 0 -> Cext fp32; 1 -> Qhi (x QSCALE); 2 -> Khi; 3 -> Vhi.
// ---------------------------------------------------------------------------
#define SZT 16384
#define GSTG (2 * SZT)
#define SMEM_GEMM (2 * GSTG)    // 64 KB

__global__ __launch_bounds__(128, 2)
void gemm_mma(float* __restrict__ Cext, int asel, int wsel0, int osel0)
{
    extern __shared__ char smem[];
    const uint32_t sb = s2u(smem);

    const int wsel = wsel0 + blockIdx.z;
    const int osel = osel0 ? (osel0 + (int)blockIdx.z) : 0;

    const __half* __restrict__ Ahi = asel ? g_ahi : g_xhi;
    const __half* __restrict__ Bhi = g_whi[wsel];

    const int tid  = threadIdx.x;
    const int lane = tid & 31;
    const int wid  = tid >> 5;
    const int wm   = wid & 1;      // 2 warp-rows x 64
    const int wn   = wid >> 1;     // 2 warp-cols x 64
    const int tn   = blockIdx.x;
    const int tm   = blockIdx.y;

    float acc[4][8][4];
#pragma unroll
    for (int i = 0; i < 4; i++)
#pragma unroll
        for (int j = 0; j < 8; j++)
#pragma unroll
            for (int k = 0; k < 4; k++) acc[i][j][k] = 0.f;

    auto load_stage = [&](int s, int buf) {
        const uint32_t base = sb + buf * GSTG;
        const int k0 = s * 64;
#pragma unroll
        for (int i = 0; i < 8; i++) {
            int e = tid + i * 128;             // 0..1023
            int row = e >> 3, c = e & 7;
            uint32_t sw = sw128((uint32_t)(row * 128 + c * 16));
            cp16(base + sw,       Ahi + (size_t)(tm * 128 + row) * DM + k0 + c * 8);
            cp16(base + SZT + sw, Bhi + (size_t)(tn * 128 + row) * DM + k0 + c * 8);
        }
    };

    load_stage(0, 0);
    CP_COMMIT();

    for (int s = 0; s < 16; s++) {
        const int buf = s & 1;
        if (s + 1 < 16) {
            load_stage(s + 1, buf ^ 1);
            CP_COMMIT();
            CP_WAIT(1);
        } else {
            CP_WAIT(0);
        }
        __syncthreads();

        const uint32_t ab = sb + buf * GSTG;

#pragma unroll
        for (int kk = 0; kk < 4; kk++) {
            uint32_t af[4][4], bf[8][2];

            const int arow = wm * 64 + (lane & 7) + ((lane >> 3) & 1) * 8;
            const int akb  = kk * 32 + ((lane >> 4) & 1) * 16;
#pragma unroll
            for (int mf = 0; mf < 4; mf++)
                ldm_x4(af[mf], ab + sw128((uint32_t)((arow + mf * 16) * 128 + akb)));

            const int brow = wn * 64 + ((lane >> 4) & 1) * 8 + (lane & 7);
            const int bkb  = kk * 32 + ((lane >> 3) & 1) * 16;
#pragma unroll
            for (int nf2 = 0; nf2 < 4; nf2++) {
                uint32_t r[4];
                ldm_x4(r, ab + SZT + sw128((uint32_t)((brow + nf2 * 16) * 128 + bkb)));
                bf[nf2 * 2][0] = r[0]; bf[nf2 * 2][1] = r[1];
                bf[nf2 * 2 + 1][0] = r[2]; bf[nf2 * 2 + 1][1] = r[3];
            }

#pragma unroll
            for (int mf = 0; mf < 4; mf++)
#pragma unroll
                for (int nf = 0; nf < 8; nf++)
                    mma_f16(acc[mf][nf], af[mf], bf[nf]);
        }
        __syncthreads();
    }

    // ---- epilogue ----
    const float sc = (osel == 1) ? QSCALE : 1.0f;
#pragma unroll
    for (int mf = 0; mf < 4; mf++) {
#pragma unroll
        for (int nf = 0; nf < 8; nf++) {
            int r0 = tm * 128 + wm * 64 + mf * 16 + (lane >> 2);
            int c0 = tn * 128 + wn * 64 + nf * 8 + (lane & 3) * 2;
#pragma unroll
            for (int half = 0; half < 2; half++) {
                int row = r0 + half * 8;
                float vx = acc[mf][nf][half * 2];
                float vy = acc[mf][nf][half * 2 + 1];
                if (osel == 0) {
                    *(float2*)(Cext + (size_t)row * DM + c0) = make_float2(vx, vy);
                } else {
                    int b = row >> 11, t = row & 2047;
                    int h = c0 >> 6,  d = c0 & 63;
                    size_t off = ((((size_t)(b * NH + h)) * TT + t) << 6) + d;
                    __half2 hv = __floats2half2_rn(vx * sc, vy * sc);
                    __half* Dst = (osel == 1) ? g_Qhi : (osel == 2) ? g_Khi : g_Vhi;
                    *(uint32_t*)(Dst + off) = *(uint32_t*)&hv;
                }
            }
        }
    }
}

// ---------------------------------------------------------------------------
// Flash attention v8: max-free chunked softmax, 16 q-rows/warp, 128-row tile,
// 3-stage KV pipeline, TWO CTAs PER SM (regs <= 128, smem 64 KB).
// 4 warps/SMSP: cross-CTA overlap fills barrier and softmax phases.
// ---------------------------------------------------------------------------
#define AKV 64
#define NKV (TT / AKV)
#define AS_Q   16384                    // Q staging 16K (128 rows x 128B)
#define AS_STG 16384                    // Khi 8K | Vhi 8K
#define SMEM_ATTN (AS_Q + 3 * AS_STG)   // 64 KB (3 KV stages)

__global__ __launch_bounds__(256, 2)
void attn_mma()
{
    extern __shared__ char smem[];
    const uint32_t sb = s2u(smem);
    const int tid = threadIdx.x, lane = tid & 31, wid = tid >> 5;
    const int bh = blockIdx.x, qt = blockIdx.y;
    const int b = bh >> 4, h = bh & 15;

    // ---- stage Q (128 rows x 128B) ----
    const size_t qg = ((size_t)bh * TT + qt * 128) * DH;
#pragma unroll
    for (int i = 0; i < 4; i++) {
        int e = tid + i * 256;
        int row = e >> 3, c = e & 7;
        cp16(sb + sw128((uint32_t)(row * 128 + c * 16)),
             g_Qhi + qg + (size_t)row * DH + c * 8);
    }
    CP_COMMIT();

    const size_t kvbase = (size_t)bh * TT * DH;
    auto load_kv = [&](int t, int buf) {
        const uint32_t base = sb + AS_Q + buf * AS_STG;
        const int kt = t * AKV;
#pragma unroll
        for (int i = 0; i < 2; i++) {
            int e = tid + i * 256;
            int row = e >> 3, c = e & 7;
            uint32_t sw = sw128((uint32_t)(row * 128 + c * 16));
            size_t g = kvbase + (size_t)(kt + row) * DH + c * 8;
            cp16(base + sw,        g_Khi + g);
            cp16(base + 8192 + sw, g_Vhi + g);
        }
    };
    load_kv(0, 0); CP_COMMIT();
    load_kv(1, 1); CP_COMMIT();

    // ---- cache Q fragments in registers (16 rows per warp) ----
    CP_WAIT(2);
    __syncthreads();
    uint32_t qf[4][4];
#pragma unroll
    for (int kk = 0; kk < 4; kk++) {
        int arow = wid * 16 + (lane & 7) + ((lane >> 3) & 1) * 8;
        int akb  = kk * 32 + ((lane >> 4) & 1) * 16;
        ldm_x4(qf[kk], sb + sw128((uint32_t)(arow * 128 + akb)));
    }

    float O[8][4];
#pragma unroll
    for (int j = 0; j < 8; j++)
#pragma unroll
        for (int k = 0; k < 4; k++) O[j][k] = 0.f;
    float Ls[4] = {0.f, 0.f, 0.f, 0.f};

    const uint32_t onesb[2] = {0x3C003C00u, 0x3C003C00u};

    for (int t = 0; t < NKV; t++) {
        if (t == NKV - 1) { CP_WAIT(0); } else { CP_WAIT(1); }
        __syncthreads();
        if (t + 2 < NKV) { load_kv(t + 2, (t + 2) % 3); CP_COMMIT(); }

        const uint32_t kb = sb + AS_Q + (t % 3) * AS_STG;

        // ---- 4 chunks of 16 keys: S -> ex2 -> PV, pipelined ----
#pragma unroll
        for (int c = 0; c < 4; c++) {
            // S for 16 keys (2 nf groups of 8)
            float S[2][4];
#pragma unroll
            for (int j = 0; j < 2; j++)
#pragma unroll
                for (int k = 0; k < 4; k++) S[j][k] = 0.f;

#pragma unroll
            for (int kk = 0; kk < 4; kk++) {
                const int brow = c * 16 + ((lane >> 4) & 1) * 8 + (lane & 7);
                const int bkb  = kk * 32 + ((lane >> 3) & 1) * 16;
                uint32_t r[4];
                ldm_x4(r, kb + sw128((uint32_t)(brow * 128 + bkb)));
                uint32_t kf0[2] = {r[0], r[1]};
                uint32_t kf1[2] = {r[2], r[3]};
                mma_f16(S[0], qf[kk], kf0);
                mma_f16(S[1], qf[kk], kf1);
            }

            // P = 2^S for this chunk
            uint32_t p[4];
            {
                __half2 a0 = __floats2half2_rn(S[0][0], S[0][1]);
                __half2 a1 = __floats2half2_rn(S[0][2], S[0][3]);
                __half2 a2 = __floats2half2_rn(S[1][0], S[1][1]);
                __half2 a3 = __floats2half2_rn(S[1][2], S[1][3]);
                p[0] = ex2h2(*(uint32_t*)&a0);
                p[1] = ex2h2(*(uint32_t*)&a1);
                p[2] = ex2h2(*(uint32_t*)&a2);
                p[3] = ex2h2(*(uint32_t*)&a3);
            }

            // PV over this 16-key chunk; l via ones-MMA
            uint32_t vf[8][2];
            const int grp = lane >> 3;
            const int vrow = c * 16 + (grp & 1) * 8 + (lane & 7);
            const int vbc  = (grp >> 1) * 16;
#pragma unroll
            for (int nf2 = 0; nf2 < 4; nf2++) {
                uint32_t r[4];
                ldm_x4_trans(r, kb + 8192 + sw128((uint32_t)(vrow * 128 + nf2 * 32 + vbc)));
                vf[nf2 * 2][0] = r[0]; vf[nf2 * 2][1] = r[1];
                vf[nf2 * 2 + 1][0] = r[2]; vf[nf2 * 2 + 1][1] = r[3];
            }
#pragma unroll
            for (int nf = 0; nf < 8; nf++)
                mma_f16(O[nf], p, vf[nf]);
            mma_f16(Ls, p, onesb);
        }
    }

    // ---- epilogue: normalize, write g_ahi ----
    float inv0 = 1.f / Ls[0];
    float inv1 = 1.f / Ls[2];
    int r0 = qt * 128 + wid * 16 + (lane >> 2);
#pragma unroll
    for (int nf = 0; nf < 8; nf++) {
        int col = h * DH + nf * 8 + (lane & 3) * 2;
        size_t off0 = ((size_t)(b * TT) + r0) * DM + col;
        __half2 h0 = __floats2half2_rn(O[nf][0] * inv0, O[nf][1] * inv0);
        *(uint32_t*)(g_ahi + off0) = *(uint32_t*)&h0;
        size_t off1 = off0 + (size_t)8 * DM;
        __half2 h1 = __floats2half2_rn(O[nf][2] * inv1, O[nf][3] * inv1);
        *(uint32_t*)(g_ahi + off1) = *(uint32_t*)&h1;
    }
}

// ---------------------------------------------------------------------------
extern "C" void kernel_launch(void* const* d_in, const int* in_sizes, int n_in,
                              void* d_out, int out_size)
{
    const float* x   = (const float*)d_in[0];
    const float* W_q = (const float*)d_in[1];
    const float* W_k = (const float*)d_in[2];
    const float* W_v = (const float*)d_in[3];
    const float* W_o = (const float*)d_in[4];
    float* out = (float*)d_out;

    cudaFuncSetAttribute(gemm_mma, cudaFuncAttributeMaxDynamicSharedMemorySize, SMEM_GEMM);
    cudaFuncSetAttribute(attn_mma, cudaFuncAttributeMaxDynamicSharedMemorySize, SMEM_ATTN);

    // fp32 -> fp16 conversions (x in 4 chunks + 4 weights, one launch)
    cvt_all<<<dim3(DM * DM / 1024, 8), 256>>>(x, W_q, W_k, W_v, W_o);

    // Q/K/V projections in one launch (1-MMA each)
    gemm_mma<<<dim3(8, 32, 3), 128, SMEM_GEMM>>>(nullptr, 0, 0, 1);

    // Max-free chunked tensor-core flash attention (2 CTAs/SM) -> g_ahi
    attn_mma<<<dim3(BATCH * NH, TT / 128), 256, SMEM_ATTN>>>();

    // Output projection (1-MMA) -> d_out
    gemm_mma<<<dim3(8, 32, 1), 128, SMEM_GEMM>>>(out, 1, 3, 0);
}